// round 9
// baseline (speedup 1.0000x reference)
#include <cuda_runtime.h>
#include <cuda_bf16.h>
#include <stdint.h>
#include <math.h>

#define NE   800000
#define NND  100000
#define HH   128
#define KIN  256
#define FF   512
#define TE   128
#define SINV (1.0f/30.0f)

// scratch: aggregated messages (51.2 MB) + prepped bf16 split weights
__device__ float g_dh[(size_t)NND * HH];
__device__ __align__(16) unsigned char g_wprep[4 * 65536];    // edge W1,W2,W3
__device__ __align__(16) unsigned char g_nwprep[8 * 65536];   // node D1(4) + D2(4)

// ===========================================================================
// helpers
// ===========================================================================
__device__ __forceinline__ uint32_t smem_u32(const void* p) {
    uint32_t a;
    asm("{ .reg .u64 t; cvta.to.shared.u64 t, %1; cvt.u32.u64 %0, t; }"
        : "=r"(a) : "l"(p));
    return a;
}

#define LDSM_X4(r0, r1, r2, r3, addr) \
    asm volatile("ldmatrix.sync.aligned.m8n8.x4.shared.b16 {%0,%1,%2,%3}, [%4];" \
        : "=r"(r0), "=r"(r1), "=r"(r2), "=r"(r3) : "r"(addr))

#define LDSM_X4T(r0, r1, r2, r3, addr) \
    asm volatile("ldmatrix.sync.aligned.m8n8.x4.trans.shared.b16 {%0,%1,%2,%3}, [%4];" \
        : "=r"(r0), "=r"(r1), "=r"(r2), "=r"(r3) : "r"(addr))

#define MMA_BF16(d, a, b0, b1) \
    asm volatile("mma.sync.aligned.m16n8k16.row.col.f32.bf16.bf16.f32 " \
        "{%0,%1,%2,%3}, {%4,%5,%6,%7}, {%8,%9}, {%0,%1,%2,%3};" \
        : "+f"((d)[0]), "+f"((d)[1]), "+f"((d)[2]), "+f"((d)[3]) \
        : "r"((a)[0]), "r"((a)[1]), "r"((a)[2]), "r"((a)[3]), "r"(b0), "r"(b1))

#define CP_WAIT(n) asm volatile("cp.async.wait_group %0;" :: "n"(n) : "memory")

// copy one 64KB weight chunk to SMEM (per-thread 16 x 16B) + commit group
__device__ __forceinline__ void cp_w(uint32_t dsts, const unsigned char* src, int tid) {
#pragma unroll
    for (int i = 0; i < 16; i++) {
        uint32_t o = (uint32_t)(tid + 256 * i) * 16u;
        asm volatile("cp.async.cg.shared.global [%0], [%1], 16;"
                     :: "r"(dsts + o), "l"(src + o) : "memory");
    }
    asm volatile("cp.async.commit_group;" ::: "memory");
}

__device__ __forceinline__ uint32_t pack_bf2(float v0, float v1) {
    __nv_bfloat16 h0 = __float2bfloat16(v0), h1 = __float2bfloat16(v1);
    return (uint32_t)__bfloat16_as_ushort(h0) | ((uint32_t)__bfloat16_as_ushort(h1) << 16);
}

// ===========================================================================
// shared GEMM machinery (validated round 8)
// ===========================================================================
// One K=128 chunk of bf16x3 MMAs: acc += A*W (3 split passes).
__device__ __forceinline__ void mma_chunk(float (*acc)[8][4], uint32_t ahi, uint32_t alo,
                                          uint32_t wb, int warpM, int warpN, int lane) {
#pragma unroll
    for (int pass = 0; pass < 3; pass++) {
        uint32_t ab = (pass == 2) ? alo : ahi;
        uint32_t bb = wb + ((pass == 1) ? 32768u : 0u) + (uint32_t)warpN * 16384u;
#pragma unroll
        for (int s = 0; s < 8; s++) {
            uint32_t a[2][4];
#pragma unroll
            for (int mi = 0; mi < 2; mi++) {
                int row = warpM * 32 + mi * 16 + (lane & 15);
                uint32_t off = ((uint32_t)(row >> 3) << 10) + ((uint32_t)(row & 7) << 7)
                             + (uint32_t)((s & 3) * 32 + ((lane >> 4) << 4));
                off ^= (off >> 3) & 0x70;
                LDSM_X4(a[mi][0], a[mi][1], a[mi][2], a[mi][3],
                        ab + (uint32_t)(s >> 2) * 16384u + off);
            }
            uint32_t b[4][4];
#pragma unroll
            for (int bt = 0; bt < 4; bt++) {
                int k = s * 16 + (lane & 15);
                uint32_t off = ((uint32_t)(k >> 3) << 10) + ((uint32_t)(k & 7) << 7)
                             + (uint32_t)(bt * 32 + ((lane >> 4) << 4));
                off ^= (off >> 3) & 0x70;
                LDSM_X4T(b[bt][0], b[bt][1], b[bt][2], b[bt][3], bb + off);
            }
#pragma unroll
            for (int mi = 0; mi < 2; mi++)
#pragma unroll
                for (int nt = 0; nt < 8; nt++)
                    MMA_BF16(acc[mi][nt], a[mi], b[nt >> 1][(nt & 1) * 2],
                             b[nt >> 1][(nt & 1) * 2 + 1]);
        }
    }
}

// Layer epilogue: relu(acc+bias) -> split hi/lo -> target slabs ([m][k]).
// Zeros acc.
__device__ __forceinline__ void epi_act(float (*acc)[8][4], uint8_t* ahi, uint8_t* alo,
                                        const float* bias, int warpM, int warpN, int lane) {
    uint32_t slab = (uint32_t)warpN * 16384u;
#pragma unroll
    for (int mi = 0; mi < 2; mi++) {
#pragma unroll
        for (int nt = 0; nt < 8; nt++) {
            int r0 = warpM * 32 + mi * 16 + (lane >> 2);
            int kk = nt * 8 + (lane & 3) * 2;
            int n  = warpN * 64 + kk;
            float b0v = bias[n], b1v = bias[n + 1];
#pragma unroll
            for (int hh = 0; hh < 2; hh++) {
                int r = r0 + hh * 8;
                float v0 = fmaxf(acc[mi][nt][hh * 2 + 0] + b0v, 0.f);
                float v1 = fmaxf(acc[mi][nt][hh * 2 + 1] + b1v, 0.f);
                __nv_bfloat16 h0 = __float2bfloat16(v0), h1 = __float2bfloat16(v1);
                float f0 = __bfloat162float(h0), f1 = __bfloat162float(h1);
                uint32_t hp = (uint32_t)__bfloat16_as_ushort(h0)
                            | ((uint32_t)__bfloat16_as_ushort(h1) << 16);
                uint32_t lp = pack_bf2(v0 - f0, v1 - f1);
                uint32_t off = ((uint32_t)(r >> 3) << 10) + ((uint32_t)(r & 7) << 7)
                             + (uint32_t)kk * 2;
                off ^= (off >> 3) & 0x70;
                *(uint32_t*)(ahi + slab + off) = hp;
                *(uint32_t*)(alo + slab + off) = lp;
            }
            acc[mi][nt][0] = 0.f; acc[mi][nt][1] = 0.f;
            acc[mi][nt][2] = 0.f; acc[mi][nt][3] = 0.f;
        }
    }
}

// ===========================================================================
__global__ void zero_dh_kernel() {
    size_t i = (size_t)blockIdx.x * blockDim.x + threadIdx.x;
    if (i < (size_t)NND * HH / 4)
        ((float4*)g_dh)[i] = make_float4(0.f, 0.f, 0.f, 0.f);
}

// Edge weights: bf16 hi/lo [k][n] slabs, SW128 swizzled.
// Chunks: 0=W1[k0:128), 1=W1[k128:256), 2=W2, 3=W3. 64KB/chunk.
__global__ void prep_w_kernel(const float* __restrict__ W1,
                              const float* __restrict__ W2,
                              const float* __restrict__ W3) {
    int t = blockIdx.x * 256 + threadIdx.x;      // 0..65535
    int c  = t >> 14;
    int r  = t & 16383;
    int n  = r & 127;
    int kl = r >> 7;
    const float* W; int kg;
    if      (c == 0) { W = W1; kg = kl; }
    else if (c == 1) { W = W1; kg = kl + 128; }
    else if (c == 2) { W = W2; kg = kl; }
    else             { W = W3; kg = kl; }
    float w = W[(size_t)kg * 128 + n];
    __nv_bfloat16 hi = __float2bfloat16(w);
    __nv_bfloat16 lo = __float2bfloat16(w - __bfloat162float(hi));
    int slab = n >> 6, nn = n & 63;
    uint32_t off = ((uint32_t)(kl >> 3) << 10) + ((uint32_t)(kl & 7) << 7) + nn * 2;
    off ^= (off >> 3) & 0x70;
    size_t base = (size_t)c * 65536 + (size_t)slab * 16384 + off;
    *(__nv_bfloat16*)(g_wprep + base) = hi;
    *(__nv_bfloat16*)(g_wprep + base + 32768) = lo;
}

// Node weights: D1 (4 chunks over n), then D2 (4 chunks over k). 64KB/chunk.
__global__ void prep_nw_kernel(const float* __restrict__ D1,
                               const float* __restrict__ D2) {
    int t = blockIdx.x * 256 + threadIdx.x;      // 0..131071
    int mat = t >> 16;
    int r   = t & 65535;
    int c   = r >> 14;          // chunk 0..3
    int e   = r & 16383;
    int n   = e & 127;
    int kl  = e >> 7;
    float w;
    if (mat == 0) w = D1[(size_t)kl * FF + c * 128 + n];
    else          w = D2[(size_t)(c * 128 + kl) * HH + n];
    __nv_bfloat16 hi = __float2bfloat16(w);
    __nv_bfloat16 lo = __float2bfloat16(w - __bfloat162float(hi));
    int slab = n >> 6, nn = n & 63;
    uint32_t off = ((uint32_t)(kl >> 3) << 10) + ((uint32_t)(kl & 7) << 7) + nn * 2;
    off ^= (off >> 3) & 0x70;
    size_t base = (size_t)mat * 262144 + (size_t)c * 65536 + (size_t)slab * 16384 + off;
    *(__nv_bfloat16*)(g_nwprep + base) = hi;
    *(__nv_bfloat16*)(g_nwprep + base + 32768) = lo;
}

// Stage a K=128 activation chunk: fp32 -> bf16 hi/lo into SW128 [m][k] slabs.
__device__ __forceinline__ void stage_A(uint8_t* smb, uint32_t of_ahi, uint32_t of_alo,
                                        const float* __restrict__ hE,
                                        size_t e0, int kc, int tid) {
#pragma unroll
    for (int it = 0; it < 16; it++) {
        int idx = tid + 256 * it;           // 0..4095 (128 rows x 32 float4)
        int r = idx >> 5, c4 = idx & 31;
        float4 v = *(const float4*)(hE + (e0 + r) * KIN + kc + c4 * 4);
        __nv_bfloat16 h0 = __float2bfloat16(v.x), h1 = __float2bfloat16(v.y);
        __nv_bfloat16 h2 = __float2bfloat16(v.z), h3 = __float2bfloat16(v.w);
        uint32_t hA = (uint32_t)__bfloat16_as_ushort(h0) | ((uint32_t)__bfloat16_as_ushort(h1) << 16);
        uint32_t hB = (uint32_t)__bfloat16_as_ushort(h2) | ((uint32_t)__bfloat16_as_ushort(h3) << 16);
        uint32_t lA = pack_bf2(v.x - __bfloat162float(h0), v.y - __bfloat162float(h1));
        uint32_t lB = pack_bf2(v.z - __bfloat162float(h2), v.w - __bfloat162float(h3));
        uint32_t off = ((uint32_t)(r >> 3) << 10) + ((uint32_t)(r & 7) << 7) + ((uint32_t)(c4 & 15) << 3);
        off ^= (off >> 3) & 0x70;
        uint32_t slab = (uint32_t)(c4 >> 4) * 16384;
        *(uint2*)(smb + of_ahi + slab + off) = make_uint2(hA, hB);
        *(uint2*)(smb + of_alo + slab + off) = make_uint2(lA, lB);
    }
}

// SMEM offsets — edge kernel
#define OF_SRC  0
#define OF_BIAS 512
#define OF_AHI  2048
#define OF_ALO  34816
#define OF_W0   67584
#define OF_W1   133120
#define SM_EDGE (198656 + 128)

// ===========================================================================
// Edge kernel: fused 3-layer MLP on HMMA (bf16x3) + vector-red scatter
// ===========================================================================
__global__ __launch_bounds__(256, 1)
void edge_mma_kernel(const float* __restrict__ hE, const int* __restrict__ eidx,
                     const float* __restrict__ b1, const float* __restrict__ b2,
                     const float* __restrict__ b3)
{
    extern __shared__ __align__(16) uint8_t sm8[];
    uint32_t sbr = smem_u32(sm8);
    uint32_t sb  = (sbr + 127u) & ~127u;
    uint8_t* smb = sm8 + (sb - sbr);

    const int tid = threadIdx.x, wid = tid >> 5, lane = tid & 31;
    const int warpM = wid & 3, warpN = wid >> 2;
    const size_t e0 = (size_t)blockIdx.x * TE;

    if (tid < 128) {
        ((int*)(smb + OF_SRC))[tid] = eidx[e0 + tid];       // row 0 = src
        float* bs = (float*)(smb + OF_BIAS);
        bs[tid] = b1[tid]; bs[128 + tid] = b2[tid]; bs[256 + tid] = b3[tid];
    }

    cp_w(sb + OF_W0, g_wprep, tid);              // G0: W1 chunk k0-127
    cp_w(sb + OF_W1, g_wprep + 65536, tid);      // G1: W1 chunk k128-255

    stage_A(smb, OF_AHI, OF_ALO, hE, e0, 0, tid);
    CP_WAIT(1);
    __syncthreads();

    float acc[2][8][4];
#pragma unroll
    for (int mi = 0; mi < 2; mi++)
#pragma unroll
        for (int nt = 0; nt < 8; nt++)
#pragma unroll
            for (int q = 0; q < 4; q++) acc[mi][nt][q] = 0.f;

    const float* bias_sm = (const float*)(smb + OF_BIAS);

    // ---- layer 1, chunk 0 ----
    mma_chunk(acc, sb + OF_AHI, sb + OF_ALO, sb + OF_W0, warpM, warpN, lane);
    __syncthreads();

    // ---- layer 1, chunk 1 ----
    cp_w(sb + OF_W0, g_wprep + 131072, tid);     // G2: W2 into buf0
    stage_A(smb, OF_AHI, OF_ALO, hE, e0, 128, tid);
    CP_WAIT(1);                                  // G1 done (G2 may pend)
    __syncthreads();
    mma_chunk(acc, sb + OF_AHI, sb + OF_ALO, sb + OF_W1, warpM, warpN, lane);
    __syncthreads();

    epi_act(acc, smb + OF_AHI, smb + OF_ALO, bias_sm, warpM, warpN, lane);
    cp_w(sb + OF_W1, g_wprep + 196608, tid);     // G3: W3 into buf1
    CP_WAIT(1);                                  // G2 done
    __syncthreads();

    // ---- layer 2 ----
    mma_chunk(acc, sb + OF_AHI, sb + OF_ALO, sb + OF_W0, warpM, warpN, lane);
    __syncthreads();
    epi_act(acc, smb + OF_AHI, smb + OF_ALO, bias_sm + 128, warpM, warpN, lane);
    CP_WAIT(0);                                  // G3 done
    __syncthreads();

    // ---- layer 3 ----
    mma_chunk(acc, sb + OF_AHI, sb + OF_ALO, sb + OF_W1, warpM, warpN, lane);

    // scatter epilogue: (acc + b3) * SINV -> red.v2 into g_dh[src]
    const int* s_src = (const int*)(smb + OF_SRC);
    const float* b3s = bias_sm + 256;
#pragma unroll
    for (int mi = 0; mi < 2; mi++) {
#pragma unroll
        for (int nt = 0; nt < 8; nt++) {
            int r0 = warpM * 32 + mi * 16 + (lane >> 2);
            int n  = warpN * 64 + nt * 8 + (lane & 3) * 2;
            float bb0 = b3s[n], bb1 = b3s[n + 1];
#pragma unroll
            for (int hh = 0; hh < 2; hh++) {
                int r = r0 + hh * 8;
                int srcn = s_src[r];
                float v0 = (acc[mi][nt][hh * 2 + 0] + bb0) * SINV;
                float v1 = (acc[mi][nt][hh * 2 + 1] + bb1) * SINV;
                float* dst = g_dh + (size_t)srcn * HH + n;
                asm volatile("red.global.add.v2.f32 [%0], {%1, %2};"
                             :: "l"(dst), "f"(v0), "f"(v1) : "memory");
            }
        }
    }
}

// ===========================================================================
// Node kernel on HMMA: h = LN(hV+dh); y = LN(h + relu(h@D1+db1)@D2 + db2)
// ===========================================================================
// SMEM offsets — node kernel
#define N_OF_A    0            // Ahi 32K | Alo 32K
#define N_OF_T    65536        // Thi 32K | Tlo 32K
#define N_OF_W    131072       // 64K weight buffer (shares region with Z)
#define N_OF_Z    131072       // fp32 [128][132] = 67584 (phase 1 / final only)
#define N_OF_MU   198784
#define N_OF_RS   199296
#define N_OF_DB1  199808       // 512 floats
#define N_OF_DB2  201856
#define N_OF_G1   202368
#define N_OF_BE1  202880
#define N_OF_G2   203392
#define N_OF_BE2  203904
#define SM_NODE   (204416 + 128)
#define LDZ 132

__global__ __launch_bounds__(256, 1)
void node_mma_kernel(const float* __restrict__ hV,
                     const float* __restrict__ db1, const float* __restrict__ db2,
                     const float* __restrict__ g1, const float* __restrict__ be1,
                     const float* __restrict__ g2, const float* __restrict__ be2,
                     float* __restrict__ out)
{
    extern __shared__ __align__(16) uint8_t sm8[];
    uint32_t sbr = smem_u32(sm8);
    uint32_t sb  = (sbr + 127u) & ~127u;
    uint8_t* smb = sm8 + (sb - sbr);

    const int tid = threadIdx.x, wid = tid >> 5, lane = tid & 31;
    const int warpM = wid & 3, warpN = wid >> 2;
    const int n0 = blockIdx.x * TE;
    const int nrem = min(TE, NND - n0);

    float* Z    = (float*)(smb + N_OF_Z);
    float* s_mu = (float*)(smb + N_OF_MU);
    float* s_rs = (float*)(smb + N_OF_RS);
    float* db1s = (float*)(smb + N_OF_DB1);
    float* db2s = (float*)(smb + N_OF_DB2);
    float* g1s  = (float*)(smb + N_OF_G1);
    float* be1s = (float*)(smb + N_OF_BE1);
    float* g2s  = (float*)(smb + N_OF_G2);
    float* be2s = (float*)(smb + N_OF_BE2);

    db1s[tid] = db1[tid]; db1s[256 + tid] = db1[256 + tid];
    if (tid < 128) {
        db2s[tid] = db2[tid];
        g1s[tid] = g1[tid]; be1s[tid] = be1[tid];
        g2s[tid] = g2[tid]; be2s[tid] = be2[tid];
    }

    // phase 1: Z = hV + dh
    for (int idx = tid; idx < TE * HH; idx += 256) {
        int r = idx >> 7, c = idx & 127;
        float v = 0.f;
        if (r < nrem) {
            size_t g = (size_t)(n0 + r) * HH + c;
            v = hV[g] + g_dh[g];
        }
        Z[r * LDZ + c] = v;
    }
    __syncthreads();

    // LN1 row stats
    if (tid < TE) {
        const float* zr = Z + tid * LDZ;
        float s = 0.f;
        for (int c = 0; c < HH; c++) s += zr[c];
        float mu = s * (1.f / HH);
        float v = 0.f;
        for (int c = 0; c < HH; c++) { float d = zr[c] - mu; v += d * d; }
        s_mu[tid] = mu;
        s_rs[tid] = rsqrtf(v * (1.f / HH) + 1e-5f);
    }
    __syncthreads();

    // h = LN1(z) -> A slabs (hi/lo)
#pragma unroll
    for (int it = 0; it < 32; it++) {
        int idx = tid + 256 * it;           // 0..8191
        int r = idx >> 6, c2 = idx & 63, c = c2 * 2;
        float mu = s_mu[r], rs = s_rs[r];
        float v0 = (Z[r * LDZ + c]     - mu) * rs * g1s[c]     + be1s[c];
        float v1 = (Z[r * LDZ + c + 1] - mu) * rs * g1s[c + 1] + be1s[c + 1];
        __nv_bfloat16 h0 = __float2bfloat16(v0), h1 = __float2bfloat16(v1);
        uint32_t hp = (uint32_t)__bfloat16_as_ushort(h0)
                    | ((uint32_t)__bfloat16_as_ushort(h1) << 16);
        uint32_t lp = pack_bf2(v0 - __bfloat162float(h0), v1 - __bfloat162float(h1));
        uint32_t slab = (uint32_t)(c >> 6) * 16384;
        uint32_t kk = (uint32_t)(c & 63);
        uint32_t off = ((uint32_t)(r >> 3) << 10) + ((uint32_t)(r & 7) << 7) + kk * 2;
        off ^= (off >> 3) & 0x70;
        *(uint32_t*)(smb + N_OF_A + slab + off) = hp;
        *(uint32_t*)(smb + N_OF_A + 32768 + slab + off) = lp;
    }
    __syncthreads();     // Z dead; W buffer may now use its region

    float acc2[2][8][4];
#pragma unroll
    for (int mi = 0; mi < 2; mi++)
#pragma unroll
        for (int nt = 0; nt < 8; nt++)
#pragma unroll
            for (int q = 0; q < 4; q++) acc2[mi][nt][q] = 0.f;

    // FFN: 4 q-chunks of 128
    for (int qc = 0; qc < 4; qc++) {
        cp_w(sb + N_OF_W, g_nwprep + (size_t)qc * 65536, tid);       // D1 chunk
        CP_WAIT(0);
        __syncthreads();

        float acc1[2][8][4];
#pragma unroll
        for (int mi = 0; mi < 2; mi++)
#pragma unroll
            for (int nt = 0; nt < 8; nt++)
#pragma unroll
                for (int q = 0; q < 4; q++) acc1[mi][nt][q] = 0.f;

        mma_chunk(acc1, sb + N_OF_A, sb + N_OF_A + 32768, sb + N_OF_W,
                  warpM, warpN, lane);
        __syncthreads();                         // all reads of W done

        epi_act(acc1, smb + N_OF_T, smb + N_OF_T + 32768, db1s + qc * 128,
                warpM, warpN, lane);
        cp_w(sb + N_OF_W, g_nwprep + 262144 + (size_t)qc * 65536, tid);  // D2 chunk
        CP_WAIT(0);
        __syncthreads();                         // T visible + W loaded

        mma_chunk(acc2, sb + N_OF_T, sb + N_OF_T + 32768, sb + N_OF_W,
                  warpM, warpN, lane);
        __syncthreads();                         // W reads done before next qc
    }

    // y = h + dh2 + db2 -> Z (W region dead again)
#pragma unroll
    for (int mi = 0; mi < 2; mi++) {
#pragma unroll
        for (int nt = 0; nt < 8; nt++) {
            int r0 = warpM * 32 + mi * 16 + (lane >> 2);
            int n  = warpN * 64 + nt * 8 + (lane & 3) * 2;
            float bb0 = db2s[n], bb1 = db2s[n + 1];
#pragma unroll
            for (int hh = 0; hh < 2; hh++) {
                int r = r0 + hh * 8;
                uint32_t slab = (uint32_t)(n >> 6) * 16384;
                uint32_t kk = (uint32_t)(n & 63);
                uint32_t off = ((uint32_t)(r >> 3) << 10) + ((uint32_t)(r & 7) << 7) + kk * 2;
                off ^= (off >> 3) & 0x70;
                uint32_t hp = *(uint32_t*)(smb + N_OF_A + slab + off);
                uint32_t lp = *(uint32_t*)(smb + N_OF_A + 32768 + slab + off);
                float h0 = __bfloat162float(__ushort_as_bfloat16((unsigned short)(hp & 0xFFFF)))
                         + __bfloat162float(__ushort_as_bfloat16((unsigned short)(lp & 0xFFFF)));
                float h1 = __bfloat162float(__ushort_as_bfloat16((unsigned short)(hp >> 16)))
                         + __bfloat162float(__ushort_as_bfloat16((unsigned short)(lp >> 16)));
                Z[r * LDZ + n]     = h0 + acc2[mi][nt][hh * 2 + 0] + bb0;
                Z[r * LDZ + n + 1] = h1 + acc2[mi][nt][hh * 2 + 1] + bb1;
            }
        }
    }
    __syncthreads();

    // LN2 row stats
    if (tid < TE) {
        const float* zr = Z + tid * LDZ;
        float s = 0.f;
        for (int c = 0; c < HH; c++) s += zr[c];
        float mu = s * (1.f / HH);
        float v = 0.f;
        for (int c = 0; c < HH; c++) { float d = zr[c] - mu; v += d * d; }
        s_mu[tid] = mu;
        s_rs[tid] = rsqrtf(v * (1.f / HH) + 1e-5f);
    }
    __syncthreads();

    for (int idx = tid; idx < TE * HH; idx += 256) {
        int r = idx >> 7, c = idx & 127;
        if (r < nrem)
            out[(size_t)(n0 + r) * HH + c] =
                (Z[r * LDZ + c] - s_mu[r]) * s_rs[r] * g2s[c] + be2s[c];
    }
}

// ===========================================================================
extern "C" void kernel_launch(void* const* d_in, const int* in_sizes, int n_in,
                              void* d_out, int out_size)
{
    const float* hV   = (const float*)d_in[0];
    const float* hE   = (const float*)d_in[1];
    const int*   eidx = (const int*)d_in[2];   // int32 [2, NE]; row 0 = src
    const float* W1  = (const float*)d_in[3];
    const float* b1  = (const float*)d_in[4];
    const float* W2  = (const float*)d_in[5];
    const float* b2  = (const float*)d_in[6];
    const float* W3  = (const float*)d_in[7];
    const float* b3  = (const float*)d_in[8];
    const float* D1  = (const float*)d_in[9];
    const float* db1 = (const float*)d_in[10];
    const float* D2  = (const float*)d_in[11];
    const float* db2 = (const float*)d_in[12];
    const float* g1  = (const float*)d_in[13];
    const float* be1 = (const float*)d_in[14];
    const float* g2  = (const float*)d_in[15];
    const float* be2 = (const float*)d_in[16];
    float* out = (float*)d_out;

    cudaFuncSetAttribute(edge_mma_kernel, cudaFuncAttributeMaxDynamicSharedMemorySize,
                         SM_EDGE);
    cudaFuncSetAttribute(node_mma_kernel, cudaFuncAttributeMaxDynamicSharedMemorySize,
                         SM_NODE);

    zero_dh_kernel<<<(NND * HH / 4 + 255) / 256, 256>>>();
    prep_w_kernel<<<256, 256>>>(W1, W2, W3);
    prep_nw_kernel<<<512, 256>>>(D1, D2);
    edge_mma_kernel<<<NE / TE, 256, SM_EDGE>>>(hE, eidx, b1, b2, b3);
    node_mma_kernel<<<(NND + TE - 1) / TE, 256, SM_NODE>>>(hV, db1, db2,
                                                           g1, be1, g2, be2, out);
}

// round 12
// speedup vs baseline: 1.8660x; 1.8660x over previous
#include <cuda_runtime.h>
#include <cuda_bf16.h>
#include <stdint.h>
#include <math.h>

#define NE   800000
#define NND  100000
#define HH   128
#define KIN  256
#define FF   512
#define TE   128
#define SINV (1.0f/30.0f)

// scratch: aggregated messages (51.2 MB) + prepped bf16 split weights
__device__ float g_dh[(size_t)NND * HH];
__device__ __align__(16) unsigned char g_wprep[4 * 65536];    // edge W1,W2,W3
__device__ __align__(16) unsigned char g_nwprep[8 * 65536];   // node D1(4) + D2(4)

// ===========================================================================
// helpers
// ===========================================================================
__device__ __forceinline__ uint32_t smem_u32(const void* p) {
    uint32_t a;
    asm("{ .reg .u64 t; cvta.to.shared.u64 t, %1; cvt.u32.u64 %0, t; }"
        : "=r"(a) : "l"(p));
    return a;
}

#define LDSM_X4(r0, r1, r2, r3, addr) \
    asm volatile("ldmatrix.sync.aligned.m8n8.x4.shared.b16 {%0,%1,%2,%3}, [%4];" \
        : "=r"(r0), "=r"(r1), "=r"(r2), "=r"(r3) : "r"(addr))

#define LDSM_X4T(r0, r1, r2, r3, addr) \
    asm volatile("ldmatrix.sync.aligned.m8n8.x4.trans.shared.b16 {%0,%1,%2,%3}, [%4];" \
        : "=r"(r0), "=r"(r1), "=r"(r2), "=r"(r3) : "r"(addr))

#define MMA_BF16(d, a, b0, b1) \
    asm volatile("mma.sync.aligned.m16n8k16.row.col.f32.bf16.bf16.f32 " \
        "{%0,%1,%2,%3}, {%4,%5,%6,%7}, {%8,%9}, {%0,%1,%2,%3};" \
        : "+f"((d)[0]), "+f"((d)[1]), "+f"((d)[2]), "+f"((d)[3]) \
        : "r"((a)[0]), "r"((a)[1]), "r"((a)[2]), "r"((a)[3]), "r"(b0), "r"(b1))

#define CP_WAIT(n) asm volatile("cp.async.wait_group %0;" :: "n"(n) : "memory")

// copy one 64KB weight chunk to SMEM (per-thread 16 x 16B) + commit group
__device__ __forceinline__ void cp_w(uint32_t dsts, const unsigned char* src, int tid) {
#pragma unroll
    for (int i = 0; i < 16; i++) {
        uint32_t o = (uint32_t)(tid + 256 * i) * 16u;
        asm volatile("cp.async.cg.shared.global [%0], [%1], 16;"
                     :: "r"(dsts + o), "l"(src + o) : "memory");
    }
    asm volatile("cp.async.commit_group;" ::: "memory");
}

__device__ __forceinline__ uint32_t pack_bf2(float v0, float v1) {
    __nv_bfloat16 h0 = __float2bfloat16(v0), h1 = __float2bfloat16(v1);
    return (uint32_t)__bfloat16_as_ushort(h0) | ((uint32_t)__bfloat16_as_ushort(h1) << 16);
}

// ===========================================================================
// edge GEMM machinery (validated round 8) — 128x128 tile, warps 4x2
// ===========================================================================
__device__ __forceinline__ void mma_chunk(float (*acc)[8][4], uint32_t ahi, uint32_t alo,
                                          uint32_t wb, int warpM, int warpN, int lane) {
#pragma unroll
    for (int pass = 0; pass < 3; pass++) {
        uint32_t ab = (pass == 2) ? alo : ahi;
        uint32_t bb = wb + ((pass == 1) ? 32768u : 0u) + (uint32_t)warpN * 16384u;
#pragma unroll
        for (int s = 0; s < 8; s++) {
            uint32_t a[2][4];
#pragma unroll
            for (int mi = 0; mi < 2; mi++) {
                int row = warpM * 32 + mi * 16 + (lane & 15);
                uint32_t off = ((uint32_t)(row >> 3) << 10) + ((uint32_t)(row & 7) << 7)
                             + (uint32_t)((s & 3) * 32 + ((lane >> 4) << 4));
                off ^= (off >> 3) & 0x70;
                LDSM_X4(a[mi][0], a[mi][1], a[mi][2], a[mi][3],
                        ab + (uint32_t)(s >> 2) * 16384u + off);
            }
            uint32_t b[4][4];
#pragma unroll
            for (int bt = 0; bt < 4; bt++) {
                int k = s * 16 + (lane & 15);
                uint32_t off = ((uint32_t)(k >> 3) << 10) + ((uint32_t)(k & 7) << 7)
                             + (uint32_t)(bt * 32 + ((lane >> 4) << 4));
                off ^= (off >> 3) & 0x70;
                LDSM_X4T(b[bt][0], b[bt][1], b[bt][2], b[bt][3], bb + off);
            }
#pragma unroll
            for (int mi = 0; mi < 2; mi++)
#pragma unroll
                for (int nt = 0; nt < 8; nt++)
                    MMA_BF16(acc[mi][nt], a[mi], b[nt >> 1][(nt & 1) * 2],
                             b[nt >> 1][(nt & 1) * 2 + 1]);
        }
    }
}

// edge layer epilogue: relu(acc+bias) -> split hi/lo -> slabs. Zeros acc.
__device__ __forceinline__ void epi_act(float (*acc)[8][4], uint8_t* ahi, uint8_t* alo,
                                        const float* bias, int warpM, int warpN, int lane) {
    uint32_t slab = (uint32_t)warpN * 16384u;
#pragma unroll
    for (int mi = 0; mi < 2; mi++) {
#pragma unroll
        for (int nt = 0; nt < 8; nt++) {
            int r0 = warpM * 32 + mi * 16 + (lane >> 2);
            int kk = nt * 8 + (lane & 3) * 2;
            int n  = warpN * 64 + kk;
            float b0v = bias[n], b1v = bias[n + 1];
#pragma unroll
            for (int hh = 0; hh < 2; hh++) {
                int r = r0 + hh * 8;
                float v0 = fmaxf(acc[mi][nt][hh * 2 + 0] + b0v, 0.f);
                float v1 = fmaxf(acc[mi][nt][hh * 2 + 1] + b1v, 0.f);
                __nv_bfloat16 h0 = __float2bfloat16(v0), h1 = __float2bfloat16(v1);
                float f0 = __bfloat162float(h0), f1 = __bfloat162float(h1);
                uint32_t hp = (uint32_t)__bfloat16_as_ushort(h0)
                            | ((uint32_t)__bfloat16_as_ushort(h1) << 16);
                uint32_t lp = pack_bf2(v0 - f0, v1 - f1);
                uint32_t off = ((uint32_t)(r >> 3) << 10) + ((uint32_t)(r & 7) << 7)
                             + (uint32_t)kk * 2;
                off ^= (off >> 3) & 0x70;
                *(uint32_t*)(ahi + slab + off) = hp;
                *(uint32_t*)(alo + slab + off) = lp;
            }
            acc[mi][nt][0] = 0.f; acc[mi][nt][1] = 0.f;
            acc[mi][nt][2] = 0.f; acc[mi][nt][3] = 0.f;
        }
    }
}

// ===========================================================================
// node GEMM machinery — 64x128 tile, warps 2x4 (warp tile 32x32)
// A slabs: 64 rows x 64 k = 8KB each, hi at +0/+8192, lo at +16384/+24576
// W slabs: same layout as edge (128k x 64n = 16KB, hi 2 slabs, lo at +32768)
// ===========================================================================
__device__ __forceinline__ void mma_chunk64(float (*acc)[4][4], uint32_t ahi, uint32_t alo,
                                            uint32_t wb, int warpM, int warpN, int lane) {
    const uint32_t colbase = (uint32_t)(warpN & 1) * 64u;
    const uint32_t wslab   = (uint32_t)(warpN >> 1) * 16384u;
#pragma unroll
    for (int pass = 0; pass < 3; pass++) {
        uint32_t ab = (pass == 2) ? alo : ahi;
        uint32_t bb = wb + ((pass == 1) ? 32768u : 0u) + wslab;
#pragma unroll
        for (int s = 0; s < 8; s++) {
            uint32_t a[2][4];
#pragma unroll
            for (int mi = 0; mi < 2; mi++) {
                int row = warpM * 32 + mi * 16 + (lane & 15);
                uint32_t off = ((uint32_t)(row >> 3) << 10) + ((uint32_t)(row & 7) << 7)
                             + (uint32_t)((s & 3) * 32 + ((lane >> 4) << 4));
                off ^= (off >> 3) & 0x70;
                LDSM_X4(a[mi][0], a[mi][1], a[mi][2], a[mi][3],
                        ab + (uint32_t)(s >> 2) * 8192u + off);
            }
            uint32_t b[2][4];
#pragma unroll
            for (int bt = 0; bt < 2; bt++) {
                int k = s * 16 + (lane & 15);
                uint32_t off = ((uint32_t)(k >> 3) << 10) + ((uint32_t)(k & 7) << 7)
                             + (colbase + (uint32_t)bt * 32 + ((lane >> 4) << 4));
                off ^= (off >> 3) & 0x70;
                LDSM_X4T(b[bt][0], b[bt][1], b[bt][2], b[bt][3], bb + off);
            }
#pragma unroll
            for (int mi = 0; mi < 2; mi++)
#pragma unroll
                for (int nt = 0; nt < 4; nt++)
                    MMA_BF16(acc[mi][nt], a[mi], b[nt >> 1][(nt & 1) * 2],
                             b[nt >> 1][(nt & 1) * 2 + 1]);
        }
    }
}

// node epilogue: relu(acc+bias) -> split hi/lo -> T slabs (64-row layout)
__device__ __forceinline__ void epi_act64(float (*acc)[4][4], uint8_t* thi, uint8_t* tlo,
                                          const float* bias, int warpM, int warpN, int lane) {
#pragma unroll
    for (int mi = 0; mi < 2; mi++) {
#pragma unroll
        for (int nt = 0; nt < 4; nt++) {
            int r0 = warpM * 32 + mi * 16 + (lane >> 2);
            int n  = warpN * 32 + nt * 8 + (lane & 3) * 2;
            uint32_t slab = (uint32_t)(n >> 6) * 8192u;
            uint32_t kk = (uint32_t)(n & 63);
            float b0v = bias[n], b1v = bias[n + 1];
#pragma unroll
            for (int hh = 0; hh < 2; hh++) {
                int r = r0 + hh * 8;
                float v0 = fmaxf(acc[mi][nt][hh * 2 + 0] + b0v, 0.f);
                float v1 = fmaxf(acc[mi][nt][hh * 2 + 1] + b1v, 0.f);
                __nv_bfloat16 h0 = __float2bfloat16(v0), h1 = __float2bfloat16(v1);
                uint32_t hp = (uint32_t)__bfloat16_as_ushort(h0)
                            | ((uint32_t)__bfloat16_as_ushort(h1) << 16);
                uint32_t lp = pack_bf2(v0 - __bfloat162float(h0), v1 - __bfloat162float(h1));
                uint32_t off = ((uint32_t)(r >> 3) << 10) + ((uint32_t)(r & 7) << 7) + kk * 2;
                off ^= (off >> 3) & 0x70;
                *(uint32_t*)(thi + slab + off) = hp;
                *(uint32_t*)(tlo + slab + off) = lp;
            }
        }
    }
}

// ===========================================================================
__global__ void zero_dh_kernel() {
    size_t i = (size_t)blockIdx.x * blockDim.x + threadIdx.x;
    if (i < (size_t)NND * HH / 4)
        ((float4*)g_dh)[i] = make_float4(0.f, 0.f, 0.f, 0.f);
}

// Edge weights: bf16 hi/lo [k][n] slabs, SW128 swizzled.
__global__ void prep_w_kernel(const float* __restrict__ W1,
                              const float* __restrict__ W2,
                              const float* __restrict__ W3) {
    int t = blockIdx.x * 256 + threadIdx.x;
    int c  = t >> 14;
    int r  = t & 16383;
    int n  = r & 127;
    int kl = r >> 7;
    const float* W; int kg;
    if      (c == 0) { W = W1; kg = kl; }
    else if (c == 1) { W = W1; kg = kl + 128; }
    else if (c == 2) { W = W2; kg = kl; }
    else             { W = W3; kg = kl; }
    float w = W[(size_t)kg * 128 + n];
    __nv_bfloat16 hi = __float2bfloat16(w);
    __nv_bfloat16 lo = __float2bfloat16(w - __bfloat162float(hi));
    int slab = n >> 6, nn = n & 63;
    uint32_t off = ((uint32_t)(kl >> 3) << 10) + ((uint32_t)(kl & 7) << 7) + nn * 2;
    off ^= (off >> 3) & 0x70;
    size_t base = (size_t)c * 65536 + (size_t)slab * 16384 + off;
    *(__nv_bfloat16*)(g_wprep + base) = hi;
    *(__nv_bfloat16*)(g_wprep + base + 32768) = lo;
}

// Node weights: D1 (4 chunks over n), then D2 (4 chunks over k). 64KB/chunk.
__global__ void prep_nw_kernel(const float* __restrict__ D1,
                               const float* __restrict__ D2) {
    int t = blockIdx.x * 256 + threadIdx.x;
    int mat = t >> 16;
    int r   = t & 65535;
    int c   = r >> 14;
    int e   = r & 16383;
    int n   = e & 127;
    int kl  = e >> 7;
    float w;
    if (mat == 0) w = D1[(size_t)kl * FF + c * 128 + n];
    else          w = D2[(size_t)(c * 128 + kl) * HH + n];
    __nv_bfloat16 hi = __float2bfloat16(w);
    __nv_bfloat16 lo = __float2bfloat16(w - __bfloat162float(hi));
    int slab = n >> 6, nn = n & 63;
    uint32_t off = ((uint32_t)(kl >> 3) << 10) + ((uint32_t)(kl & 7) << 7) + nn * 2;
    off ^= (off >> 3) & 0x70;
    size_t base = (size_t)mat * 262144 + (size_t)c * 65536 + (size_t)slab * 16384 + off;
    *(__nv_bfloat16*)(g_nwprep + base) = hi;
    *(__nv_bfloat16*)(g_nwprep + base + 32768) = lo;
}

// Stage a K=128 edge activation chunk: fp32 -> bf16 hi/lo into SW128 [m][k] slabs.
__device__ __forceinline__ void stage_A(uint8_t* smb, uint32_t of_ahi, uint32_t of_alo,
                                        const float* __restrict__ hE,
                                        size_t e0, int kc, int tid) {
#pragma unroll
    for (int it = 0; it < 16; it++) {
        int idx = tid + 256 * it;
        int r = idx >> 5, c4 = idx & 31;
        float4 v = *(const float4*)(hE + (e0 + r) * KIN + kc + c4 * 4);
        __nv_bfloat16 h0 = __float2bfloat16(v.x), h1 = __float2bfloat16(v.y);
        __nv_bfloat16 h2 = __float2bfloat16(v.z), h3 = __float2bfloat16(v.w);
        uint32_t hA = (uint32_t)__bfloat16_as_ushort(h0) | ((uint32_t)__bfloat16_as_ushort(h1) << 16);
        uint32_t hB = (uint32_t)__bfloat16_as_ushort(h2) | ((uint32_t)__bfloat16_as_ushort(h3) << 16);
        uint32_t lA = pack_bf2(v.x - __bfloat162float(h0), v.y - __bfloat162float(h1));
        uint32_t lB = pack_bf2(v.z - __bfloat162float(h2), v.w - __bfloat162float(h3));
        uint32_t off = ((uint32_t)(r >> 3) << 10) + ((uint32_t)(r & 7) << 7) + ((uint32_t)(c4 & 15) << 3);
        off ^= (off >> 3) & 0x70;
        uint32_t slab = (uint32_t)(c4 >> 4) * 16384;
        *(uint2*)(smb + of_ahi + slab + off) = make_uint2(hA, hB);
        *(uint2*)(smb + of_alo + slab + off) = make_uint2(lA, lB);
    }
}

// SMEM offsets — edge kernel
#define OF_SRC  0
#define OF_BIAS 512
#define OF_AHI  2048
#define OF_ALO  34816
#define OF_W0   67584
#define OF_W1   133120
#define SM_EDGE (198656 + 128)

// ===========================================================================
// Edge kernel (validated round 8): fused 3-layer MLP on HMMA + red scatter
// ===========================================================================
__global__ __launch_bounds__(256, 1)
void edge_mma_kernel(const float* __restrict__ hE, const int* __restrict__ eidx,
                     const float* __restrict__ b1, const float* __restrict__ b2,
                     const float* __restrict__ b3)
{
    extern __shared__ __align__(16) uint8_t sm8[];
    uint32_t sbr = smem_u32(sm8);
    uint32_t sb  = (sbr + 127u) & ~127u;
    uint8_t* smb = sm8 + (sb - sbr);

    const int tid = threadIdx.x, wid = tid >> 5, lane = tid & 31;
    const int warpM = wid & 3, warpN = wid >> 2;
    const size_t e0 = (size_t)blockIdx.x * TE;

    if (tid < 128) {
        ((int*)(smb + OF_SRC))[tid] = eidx[e0 + tid];       // row 0 = src
        float* bs = (float*)(smb + OF_BIAS);
        bs[tid] = b1[tid]; bs[128 + tid] = b2[tid]; bs[256 + tid] = b3[tid];
    }

    cp_w(sb + OF_W0, g_wprep, tid);              // G0: W1 chunk k0-127
    cp_w(sb + OF_W1, g_wprep + 65536, tid);      // G1: W1 chunk k128-255

    stage_A(smb, OF_AHI, OF_ALO, hE, e0, 0, tid);
    CP_WAIT(1);
    __syncthreads();

    float acc[2][8][4];
#pragma unroll
    for (int mi = 0; mi < 2; mi++)
#pragma unroll
        for (int nt = 0; nt < 8; nt++)
#pragma unroll
            for (int q = 0; q < 4; q++) acc[mi][nt][q] = 0.f;

    const float* bias_sm = (const float*)(smb + OF_BIAS);

    mma_chunk(acc, sb + OF_AHI, sb + OF_ALO, sb + OF_W0, warpM, warpN, lane);
    __syncthreads();

    cp_w(sb + OF_W0, g_wprep + 131072, tid);     // G2: W2 into buf0
    stage_A(smb, OF_AHI, OF_ALO, hE, e0, 128, tid);
    CP_WAIT(1);
    __syncthreads();
    mma_chunk(acc, sb + OF_AHI, sb + OF_ALO, sb + OF_W1, warpM, warpN, lane);
    __syncthreads();

    epi_act(acc, smb + OF_AHI, smb + OF_ALO, bias_sm, warpM, warpN, lane);
    cp_w(sb + OF_W1, g_wprep + 196608, tid);     // G3: W3 into buf1
    CP_WAIT(1);
    __syncthreads();

    mma_chunk(acc, sb + OF_AHI, sb + OF_ALO, sb + OF_W0, warpM, warpN, lane);
    __syncthreads();
    epi_act(acc, smb + OF_AHI, smb + OF_ALO, bias_sm + 128, warpM, warpN, lane);
    CP_WAIT(0);
    __syncthreads();

    mma_chunk(acc, sb + OF_AHI, sb + OF_ALO, sb + OF_W1, warpM, warpN, lane);

    const int* s_src = (const int*)(smb + OF_SRC);
    const float* b3s = bias_sm + 256;
#pragma unroll
    for (int mi = 0; mi < 2; mi++) {
#pragma unroll
        for (int nt = 0; nt < 8; nt++) {
            int r0 = warpM * 32 + mi * 16 + (lane >> 2);
            int n  = warpN * 64 + nt * 8 + (lane & 3) * 2;
            float bb0 = b3s[n], bb1 = b3s[n + 1];
#pragma unroll
            for (int hh = 0; hh < 2; hh++) {
                int r = r0 + hh * 8;
                int srcn = s_src[r];
                float v0 = (acc[mi][nt][hh * 2 + 0] + bb0) * SINV;
                float v1 = (acc[mi][nt][hh * 2 + 1] + bb1) * SINV;
                float* dst = g_dh + (size_t)srcn * HH + n;
                asm volatile("red.global.add.v2.f32 [%0], {%1, %2};"
                             :: "l"(dst), "f"(v0), "f"(v1) : "memory");
            }
        }
    }
}

// ===========================================================================
// Node kernel on HMMA, M=64 tile: h = LN(hV+dh); y = LN(h + FFN(h))
// ===========================================================================
#define N_OF_A    0            // A hi 16K (2x8K slabs), lo at +16384
#define N_OF_T    32768        // T hi 16K, lo at +16384
#define N_OF_W0   65536        // 64K: D1 chunks
#define N_OF_W1   131072       // 64K: D2 chunks; Z overlays (dead phases)
#define N_OF_Z    131072       // fp32 [64][132] = 33792
#define N_OF_MU   196608
#define N_OF_RS   196864
#define N_OF_DB1  197120       // 512 floats
#define N_OF_DB2  199168
#define N_OF_G1   199680
#define N_OF_BE1  200192
#define N_OF_G2   200704
#define N_OF_BE2  201216
#define SM_NODE   (201728 + 128)
#define LDZ 132

__global__ __launch_bounds__(256, 1)
void node_mma64_kernel(const float* __restrict__ hV,
                       const float* __restrict__ db1, const float* __restrict__ db2,
                       const float* __restrict__ g1, const float* __restrict__ be1,
                       const float* __restrict__ g2, const float* __restrict__ be2,
                       float* __restrict__ out)
{
    extern __shared__ __align__(16) uint8_t sm8[];
    uint32_t sbr = smem_u32(sm8);
    uint32_t sb  = (sbr + 127u) & ~127u;
    uint8_t* smb = sm8 + (sb - sbr);

    const int tid = threadIdx.x, wid = tid >> 5, lane = tid & 31;
    const int warpM = wid & 1, warpN = wid >> 1;     // 2 x 4 warp grid
    const int n0 = blockIdx.x * 64;
    const int nrem = min(64, NND - n0);

    float* Z    = (float*)(smb + N_OF_Z);
    float* s_mu = (float*)(smb + N_OF_MU);
    float* s_rs = (float*)(smb + N_OF_RS);
    float* db1s = (float*)(smb + N_OF_DB1);
    float* db2s = (float*)(smb + N_OF_DB2);
    float* g1s  = (float*)(smb + N_OF_G1);
    float* be1s = (float*)(smb + N_OF_BE1);
    float* g2s  = (float*)(smb + N_OF_G2);
    float* be2s = (float*)(smb + N_OF_BE2);

    // prefetch first D1 chunk into W0 (W1/Z region untouched)
    cp_w(sb + N_OF_W0, g_nwprep, tid);               // G0

    db1s[tid] = db1[tid]; db1s[256 + tid] = db1[256 + tid];
    if (tid < 128) {
        db2s[tid] = db2[tid];
        g1s[tid] = g1[tid]; be1s[tid] = be1[tid];
        g2s[tid] = g2[tid]; be2s[tid] = be2[tid];
    }

    // phase 1: Z = hV + dh  (64 rows)
#pragma unroll
    for (int it = 0; it < 32; it++) {
        int idx = tid + 256 * it;
        int r = idx >> 7, c = idx & 127;
        float v = 0.f;
        if (r < nrem) {
            size_t g = (size_t)(n0 + r) * HH + c;
            v = hV[g] + g_dh[g];
        }
        Z[r * LDZ + c] = v;
    }
    __syncthreads();

    // LN1 row stats
    if (tid < 64) {
        const float* zr = Z + tid * LDZ;
        float s = 0.f;
        for (int c = 0; c < HH; c++) s += zr[c];
        float mu = s * (1.f / HH);
        float v = 0.f;
        for (int c = 0; c < HH; c++) { float d = zr[c] - mu; v += d * d; }
        s_mu[tid] = mu;
        s_rs[tid] = rsqrtf(v * (1.f / HH) + 1e-5f);
    }
    __syncthreads();

    // h = LN1(z) -> A slabs (hi/lo), 64 rows
#pragma unroll
    for (int it = 0; it < 16; it++) {
        int idx = tid + 256 * it;        // 0..4095 pairs
        int r = idx >> 6, c = (idx & 63) * 2;
        float mu = s_mu[r], rs = s_rs[r];
        float v0 = (Z[r * LDZ + c]     - mu) * rs * g1s[c]     + be1s[c];
        float v1 = (Z[r * LDZ + c + 1] - mu) * rs * g1s[c + 1] + be1s[c + 1];
        __nv_bfloat16 h0 = __float2bfloat16(v0), h1 = __float2bfloat16(v1);
        uint32_t hp = (uint32_t)__bfloat16_as_ushort(h0)
                    | ((uint32_t)__bfloat16_as_ushort(h1) << 16);
        uint32_t lp = pack_bf2(v0 - __bfloat162float(h0), v1 - __bfloat162float(h1));
        uint32_t slab = (uint32_t)(c >> 6) * 8192;
        uint32_t kk = (uint32_t)(c & 63);
        uint32_t off = ((uint32_t)(r >> 3) << 10) + ((uint32_t)(r & 7) << 7) + kk * 2;
        off ^= (off >> 3) & 0x70;
        *(uint32_t*)(smb + N_OF_A + slab + off) = hp;
        *(uint32_t*)(smb + N_OF_A + 16384 + slab + off) = lp;
    }
    __syncthreads();     // Z dead; W1 region may now be written

    float acc2[2][4][4];
#pragma unroll
    for (int mi = 0; mi < 2; mi++)
#pragma unroll
        for (int nt = 0; nt < 4; nt++)
#pragma unroll
            for (int q = 0; q < 4; q++) acc2[mi][nt][q] = 0.f;

    // FFN: 4 q-chunks of 128, double-buffered weights (W0=D1, W1=D2)
    for (int qc = 0; qc < 4; qc++) {
        cp_w(sb + N_OF_W1, g_nwprep + 262144 + (size_t)qc * 65536, tid);  // D2[qc]
        CP_WAIT(1);                      // D1[qc] in W0 ready
        __syncthreads();

        float acc1[2][4][4];
#pragma unroll
        for (int mi = 0; mi < 2; mi++)
#pragma unroll
            for (int nt = 0; nt < 4; nt++)
#pragma unroll
                for (int q = 0; q < 4; q++) acc1[mi][nt][q] = 0.f;

        mma_chunk64(acc1, sb + N_OF_A, sb + N_OF_A + 16384, sb + N_OF_W0,
                    warpM, warpN, lane);
        __syncthreads();                 // W0 reads done before refill

        epi_act64(acc1, smb + N_OF_T, smb + N_OF_T + 16384, db1s + qc * 128,
                  warpM, warpN, lane);
        if (qc < 3) {
            cp_w(sb + N_OF_W0, g_nwprep + (size_t)(qc + 1) * 65536, tid);  // D1[qc+1]
            CP_WAIT(1);                  // D2[qc] in W1 ready
        } else {
            CP_WAIT(0);
        }
        __syncthreads();                 // T visible + W1 ready

        mma_chunk64(acc2, sb + N_OF_T, sb + N_OF_T + 16384, sb + N_OF_W1,
                    warpM, warpN, lane);
        __syncthreads();                 // W1 reads done before next D2 copy
    }

    // y = h + dh2 + db2 -> Z (W1 region dead again)
#pragma unroll
    for (int mi = 0; mi < 2; mi++) {
#pragma unroll
        for (int nt = 0; nt < 4; nt++) {
            int r0 = warpM * 32 + mi * 16 + (lane >> 2);
            int n  = warpN * 32 + nt * 8 + (lane & 3) * 2;
            float bb0 = db2s[n], bb1 = db2s[n + 1];
            uint32_t slab = (uint32_t)(n >> 6) * 8192;
            uint32_t kk = (uint32_t)(n & 63);
#pragma unroll
            for (int hh = 0; hh < 2; hh++) {
                int r = r0 + hh * 8;
                uint32_t off = ((uint32_t)(r >> 3) << 10) + ((uint32_t)(r & 7) << 7) + kk * 2;
                off ^= (off >> 3) & 0x70;
                uint32_t hp = *(uint32_t*)(smb + N_OF_A + slab + off);
                uint32_t lp = *(uint32_t*)(smb + N_OF_A + 16384 + slab + off);
                float h0 = __bfloat162float(__ushort_as_bfloat16((unsigned short)(hp & 0xFFFF)))
                         + __bfloat162float(__ushort_as_bfloat16((unsigned short)(lp & 0xFFFF)));
                float h1 = __bfloat162float(__ushort_as_bfloat16((unsigned short)(hp >> 16)))
                         + __bfloat162float(__ushort_as_bfloat16((unsigned short)(lp >> 16)));
                Z[r * LDZ + n]     = h0 + acc2[mi][nt][hh * 2 + 0] + bb0;
                Z[r * LDZ + n + 1] = h1 + acc2[mi][nt][hh * 2 + 1] + bb1;
            }
        }
    }
    __syncthreads();

    // LN2 row stats
    if (tid < 64) {
        const float* zr = Z + tid * LDZ;
        float s = 0.f;
        for (int c = 0; c < HH; c++) s += zr[c];
        float mu = s * (1.f / HH);
        float v = 0.f;
        for (int c = 0; c < HH; c++) { float d = zr[c] - mu; v += d * d; }
        s_mu[tid] = mu;
        s_rs[tid] = rsqrtf(v * (1.f / HH) + 1e-5f);
    }
    __syncthreads();

#pragma unroll
    for (int it = 0; it < 32; it++) {
        int idx = tid + 256 * it;
        int r = idx >> 7, c = idx & 127;
        if (r < nrem)
            out[(size_t)(n0 + r) * HH + c] =
                (Z[r * LDZ + c] - s_mu[r]) * s_rs[r] * g2s[c] + be2s[c];
    }
}

// ===========================================================================
extern "C" void kernel_launch(void* const* d_in, const int* in_sizes, int n_in,
                              void* d_out, int out_size)
{
    const float* hV   = (const float*)d_in[0];
    const float* hE   = (const float*)d_in[1];
    const int*   eidx = (const int*)d_in[2];   // int32 [2, NE]; row 0 = src
    const float* W1  = (const float*)d_in[3];
    const float* b1  = (const float*)d_in[4];
    const float* W2  = (const float*)d_in[5];
    const float* b2  = (const float*)d_in[6];
    const float* W3  = (const float*)d_in[7];
    const float* b3  = (const float*)d_in[8];
    const float* D1  = (const float*)d_in[9];
    const float* db1 = (const float*)d_in[10];
    const float* D2  = (const float*)d_in[11];
    const float* db2 = (const float*)d_in[12];
    const float* g1  = (const float*)d_in[13];
    const float* be1 = (const float*)d_in[14];
    const float* g2  = (const float*)d_in[15];
    const float* be2 = (const float*)d_in[16];
    float* out = (float*)d_out;

    cudaFuncSetAttribute(edge_mma_kernel, cudaFuncAttributeMaxDynamicSharedMemorySize,
                         SM_EDGE);
    cudaFuncSetAttribute(node_mma64_kernel, cudaFuncAttributeMaxDynamicSharedMemorySize,
                         SM_NODE);

    zero_dh_kernel<<<(NND * HH / 4 + 255) / 256, 256>>>();
    prep_w_kernel<<<256, 256>>>(W1, W2, W3);
    prep_nw_kernel<<<512, 256>>>(D1, D2);
    edge_mma_kernel<<<NE / TE, 256, SM_EDGE>>>(hE, eidx, b1, b2, b3);
    node_mma64_kernel<<<(NND + 63) / 64, 256, SM_NODE>>>(hV, db1, db2,
                                                         g1, be1, g2, be2, out);
}